// round 6
// baseline (speedup 1.0000x reference)
#include <cuda_runtime.h>

// ---------------- scratch (device globals; zero-initialized) ---------------
__device__ float g_pooledp[16*256*32];     // [b][cs][32] padded, pads stay 0
__device__ float g_dots[1281];             // Wq^T bk | Wk^T bq | bq.bk
__device__ float g_wqk[1024*256];          // Wq^T Wk  [cr][cs]
__device__ float g_kq[16*1024*32];         // [b][cr][32]
__device__ float g_v[16*1024*32];          // [b][cr][32]
__device__ float g_bqk[16*32];             // [b][32]
__device__ float g_epart[4*16*784*32];     // [z][b][n][32]
__device__ float g_attn_t[16*25*784];      // [b][s][n]  TRANSPOSED attention

// ---------------- packed f32x2 helpers -------------------------------------
__device__ __forceinline__ unsigned long long pack2(float lo, float hi) {
    unsigned long long r;
    asm("mov.b64 %0, {%1,%2};" : "=l"(r) : "f"(lo), "f"(hi));
    return r;
}
__device__ __forceinline__ float2 unpack2(unsigned long long v) {
    float2 r;
    asm("mov.b64 {%0,%1}, %2;" : "=f"(r.x), "=f"(r.y) : "l"(v));
    return r;
}
__device__ __forceinline__ void fma2(unsigned long long& d,
                                     unsigned long long a,
                                     unsigned long long b) {
    asm("fma.rn.f32x2 %0, %1, %2, %0;" : "+l"(d) : "l"(a), "l"(b));
}

// ---------------------------------------------------------------------------
// k_prep: gemm0 (blocks 0..127) | dots (128..138) | pool (139..1738)
// ---------------------------------------------------------------------------
__global__ __launch_bounds__(128) void k_prep(const float* __restrict__ Wq,
                                              const float* __restrict__ bq,
                                              const float* __restrict__ Wk,
                                              const float* __restrict__ bk,
                                              const float* __restrict__ xs_in) {
    __shared__ float sm[1664];
    int bid = blockIdx.x;
    int t = threadIdx.x;

    if (bid < 128) {
        float* As = sm;          // [16][64]
        float* Bs = sm + 1024;   // [16][32]
        int m0 = (bid >> 3) * 64, n0 = (bid & 7) * 32;
        int tx = t & 7, ty = t >> 3;
        unsigned long long acc2[4][2] = {};
        for (int k0 = 0; k0 < 512; k0 += 16) {
            #pragma unroll
            for (int u = 0; u < 8; u++) {
                int idx = t + u * 128;
                int kk = idx >> 6, mm = idx & 63;
                As[kk*64 + mm] = Wq[(k0+kk)*1024 + m0 + mm];
            }
            #pragma unroll
            for (int u = 0; u < 4; u++) {
                int idx = t + u * 128;
                int kk = idx >> 5, nn = idx & 31;
                Bs[kk*32 + nn] = Wk[(k0+kk)*256 + n0 + nn];
            }
            __syncthreads();
            #pragma unroll
            for (int kk = 0; kk < 16; kk++) {
                float4 a4 = *(const float4*)&As[kk*64 + ty*4];
                ulonglong2 b2 = *(const ulonglong2*)&Bs[kk*32 + tx*4];
                unsigned long long pa[4] = {pack2(a4.x,a4.x), pack2(a4.y,a4.y),
                                            pack2(a4.z,a4.z), pack2(a4.w,a4.w)};
                #pragma unroll
                for (int i = 0; i < 4; i++) {
                    fma2(acc2[i][0], pa[i], b2.x);
                    fma2(acc2[i][1], pa[i], b2.y);
                }
            }
            __syncthreads();
        }
        #pragma unroll
        for (int i = 0; i < 4; i++) {
            float2 p0 = unpack2(acc2[i][0]), p1 = unpack2(acc2[i][1]);
            *(float4*)&g_wqk[(m0 + ty*4 + i)*256 + n0 + tx*4] =
                make_float4(p0.x, p0.y, p1.x, p1.y);
        }
    } else if (bid < 136) {
        int c = (bid - 128) * 128 + t;
        float acc = 0.f;
        for (int i = 0; i < 512; i++) acc += Wq[i*1024 + c] * bk[i];
        g_dots[c] = acc;
    } else if (bid < 138) {
        int c = (bid - 136) * 128 + t;
        float acc = 0.f;
        for (int i = 0; i < 512; i++) acc += Wk[i*256 + c] * bq[i];
        g_dots[1024 + c] = acc;
    } else if (bid == 138) {
        float acc = 0.f;
        for (int i = t; i < 512; i += 128) acc += bq[i] * bk[i];
        sm[t] = acc; __syncthreads();
        for (int st = 64; st > 0; st >>= 1) {
            if (t < st) sm[t] += sm[t + st];
            __syncthreads();
        }
        if (t == 0) g_dots[1280] = sm[0];
    } else {
        int r0 = (bid - 139) * 64;
        const float* src = xs_in + (size_t)r0 * 25;
        for (int i = t; i < 1600; i += 128) sm[i] = src[i];
        __syncthreads();
        if (t < 64) {
            float s = 0.f;
            #pragma unroll
            for (int w = 0; w < 25; w++) s += sm[t*25 + w];
            int o = r0 + t;
            int bc = o / 25, s_idx = o - bc * 25;
            g_pooledp[bc*32 + s_idx] = s * (1.0f / 25.0f);
        }
    }
}

// ---------------------------------------------------------------------------
// k_gemm1: [kq; v; bqk](b) = [Wqk; Wv; wkbq] @ pooledp_b + bias
// grid(17, 16), 128 thr. BM=128, S=32, BK=32. thread 8m x 4s.
// ---------------------------------------------------------------------------
__global__ __launch_bounds__(128) void k_gemm1(const float* __restrict__ Wv,
                                               const float* __restrict__ bv) {
    __shared__ float As[32*132];
    __shared__ float Bs[32*32];
    int bx = blockIdx.x;
    int b  = blockIdx.y;
    int m0 = bx * 128;
    int t = threadIdx.x;
    int tx = t & 7, ty = t >> 3;
    unsigned long long acc2[8][2] = {};

    const float* arow;
    if (bx < 8)       arow = g_wqk + (size_t)(m0 + t) * 256;
    else if (bx < 16) arow = Wv + (size_t)(m0 - 1024 + t) * 256;
    else              arow = g_dots + 1024;

    for (int k0 = 0; k0 < 256; k0 += 32) {
        if (bx < 16 || t == 0) {
            #pragma unroll
            for (int u = 0; u < 8; u++) {
                float4 a4 = *(const float4*)&arow[k0 + u*4];
                As[(u*4+0)*132 + t] = a4.x;
                As[(u*4+1)*132 + t] = a4.y;
                As[(u*4+2)*132 + t] = a4.z;
                As[(u*4+3)*132 + t] = a4.w;
            }
        } else {
            #pragma unroll
            for (int u = 0; u < 32; u++) As[u*132 + t] = 0.f;
        }
        const float4* bsrc = (const float4*)(g_pooledp + ((b << 8) + k0) * 32);
        float4* bs4 = (float4*)Bs;
        bs4[t] = bsrc[t];
        bs4[t + 128] = bsrc[t + 128];
        __syncthreads();
        #pragma unroll 8
        for (int kk = 0; kk < 32; kk++) {
            float4 alo = *(const float4*)&As[kk*132 + ty*8];
            float4 ahi = *(const float4*)&As[kk*132 + ty*8 + 4];
            ulonglong2 b2 = *(const ulonglong2*)&Bs[kk*32 + tx*4];
            unsigned long long pa[8] = {
                pack2(alo.x,alo.x), pack2(alo.y,alo.y),
                pack2(alo.z,alo.z), pack2(alo.w,alo.w),
                pack2(ahi.x,ahi.x), pack2(ahi.y,ahi.y),
                pack2(ahi.z,ahi.z), pack2(ahi.w,ahi.w)};
            #pragma unroll
            for (int i = 0; i < 8; i++) {
                fma2(acc2[i][0], pa[i], b2.x);
                fma2(acc2[i][1], pa[i], b2.y);
            }
        }
        __syncthreads();
    }
    int s0 = tx * 4;
    #pragma unroll
    for (int i = 0; i < 8; i++) {
        int m = m0 + ty*8 + i;
        float2 p0 = unpack2(acc2[i][0]), p1 = unpack2(acc2[i][1]);
        if (bx < 8) {
            float d = g_dots[m];
            *(float4*)&g_kq[((b << 10) + m)*32 + s0] =
                make_float4(p0.x+d, p0.y+d, p1.x+d, p1.y+d);
        } else if (bx < 16) {
            float d = bv[m - 1024];
            *(float4*)&g_v[((b << 10) + (m - 1024))*32 + s0] =
                make_float4(p0.x+d, p0.y+d, p1.x+d, p1.y+d);
        } else if (m == 2048) {
            float d = g_dots[1280];
            *(float4*)&g_bqk[b*32 + s0] =
                make_float4(p0.x+d, p0.y+d, p1.x+d, p1.y+d);
        }
    }
}

// ---------------------------------------------------------------------------
// k_energy: epart[z,b,n,s] = sum_{c in z-chunk} x[c,n]*kq[c,s]
// grid(7 n-tiles of 112, 16 b, 4 z), 224 thr. thread 4n x 4s.
// ---------------------------------------------------------------------------
__global__ __launch_bounds__(224) void k_energy(const float* __restrict__ x) {
    __shared__ float xs[64*112];
    __shared__ float kqs[64*32];
    int n0 = blockIdx.x * 112;
    int b  = blockIdx.y;
    int z  = blockIdx.z;
    int t = threadIdx.x;
    int nq = t % 28, sg = t / 28;
    unsigned long long acc2[4][2] = {};

    for (int cz = 0; cz < 4; cz++) {
        int cbase = z * 256 + cz * 64;
        const float4* xsrc = (const float4*)x
            + (size_t)((b << 10) + cbase) * 196 + (n0 >> 2);
        #pragma unroll
        for (int u = 0; u < 8; u++) {
            int cc = sg + u * 8;
            *(float4*)&xs[cc*112 + nq*4] = xsrc[(size_t)cc*196 + nq];
        }
        const float4* kq4 = (const float4*)(g_kq + (size_t)((b << 10) + cbase)*32);
        float4* kqs4 = (float4*)kqs;
        kqs4[t] = kq4[t];
        if (t + 224 < 512) kqs4[t + 224] = kq4[t + 224];
        if (t < 512 - 448) kqs4[t + 448] = kq4[t + 448];
        __syncthreads();
        #pragma unroll 8
        for (int cc = 0; cc < 64; cc++) {
            float4 x4 = *(const float4*)&xs[cc*112 + nq*4];
            ulonglong2 k2 = *(const ulonglong2*)&kqs[cc*32 + sg*4];
            unsigned long long px[4] = {pack2(x4.x,x4.x), pack2(x4.y,x4.y),
                                        pack2(x4.z,x4.z), pack2(x4.w,x4.w)};
            #pragma unroll
            for (int i = 0; i < 4; i++) {
                fma2(acc2[i][0], px[i], k2.x);
                fma2(acc2[i][1], px[i], k2.y);
            }
        }
        __syncthreads();
    }
    float* ep = g_epart + (size_t)(z*16 + b)*784*32;
    #pragma unroll
    for (int i = 0; i < 4; i++) {
        int n = n0 + nq*4 + i;
        float2 p0 = unpack2(acc2[i][0]), p1 = unpack2(acc2[i][1]);
        *(float4*)&ep[(size_t)n*32 + sg*4] = make_float4(p0.x, p0.y, p1.x, p1.y);
    }
}

// ---------------------------------------------------------------------------
// k_softmax: 4 threads/pixel, split over s, quad shfl reduce.
// Writes TRANSPOSED attn [b][s][n]. grid(196), 256 thr.
// ---------------------------------------------------------------------------
__global__ __launch_bounds__(256) void k_softmax() {
    int t = threadIdx.x;
    int gp = blockIdx.x * 64 + (t >> 2);
    int q = t & 3;
    int b = gp / 784, n = gp - b * 784;

    const size_t part = (size_t)16*784*32;
    const float* base = g_epart + ((size_t)b*784 + n)*32 + q*8;
    float4 lo = *(const float4*)base;
    float4 hi = *(const float4*)(base + 4);
    #pragma unroll
    for (int z = 1; z < 4; z++) {
        float4 l2 = *(const float4*)(base + z*part);
        float4 h2 = *(const float4*)(base + z*part + 4);
        lo.x += l2.x; lo.y += l2.y; lo.z += l2.z; lo.w += l2.w;
        hi.x += h2.x; hi.y += h2.y; hi.z += h2.z; hi.w += h2.w;
    }
    float e[8] = {lo.x, lo.y, lo.z, lo.w, hi.x, hi.y, hi.z, hi.w};
    #pragma unroll
    for (int i = 0; i < 8; i++) {
        int s = q*8 + i;
        e[i] = (s < 25) ? e[i] + g_bqk[b*32 + s] : -1e30f;
    }
    float mx = e[0];
    #pragma unroll
    for (int i = 1; i < 8; i++) mx = fmaxf(mx, e[i]);
    mx = fmaxf(mx, __shfl_xor_sync(0xffffffffu, mx, 1));
    mx = fmaxf(mx, __shfl_xor_sync(0xffffffffu, mx, 2));
    float sum = 0.f;
    #pragma unroll
    for (int i = 0; i < 8; i++) { e[i] = __expf(e[i] - mx); sum += e[i]; }
    sum += __shfl_xor_sync(0xffffffffu, sum, 1);
    sum += __shfl_xor_sync(0xffffffffu, sum, 2);
    float inv = 1.f / sum;
    float* at = g_attn_t + (size_t)b*25*784 + n;
    #pragma unroll
    for (int i = 0; i < 8; i++) {
        int s = q*8 + i;
        if (s < 25) at[(size_t)s*784] = e[i] * inv;
    }
}

// ---------------------------------------------------------------------------
// k_out: out[c,n] = x[c,n] + gamma * sum_s v[c,s]*attn_t[s,n]
// grid(7 n-tiles of 112, 8 c-tiles of 128, 16 b), 256 thr (8 warps).
// Warp owns 14 pixels (attn = warp-uniform broadcast); lane owns 4 c.
// ---------------------------------------------------------------------------
__global__ __launch_bounds__(256, 2) void k_out(const float* __restrict__ x,
                                                const float* __restrict__ gamma_p,
                                                float* __restrict__ out) {
    __shared__ float attn_ts[25*112];   // [s][n] straight coalesced copy
    __shared__ float v_ts[25*132];      // [s][c] transpose load
    int n0 = blockIdx.x * 112;
    int c0 = blockIdx.y * 128;
    int b  = blockIdx.z;
    int t = threadIdx.x;

    // attn: 25 rows x 28 float4
    const float4* at4 = (const float4*)(g_attn_t + (size_t)b*25*784 + n0);
    #pragma unroll
    for (int u = 0; u < 3; u++) {
        int i = t + u*256;
        if (i < 700) {
            int s = i / 28, q = i - s*28;
            ((float4*)attn_ts)[s*28 + q] = at4[(size_t)s*196 + q];
        }
    }
    // v: 128 rows x 8 quads, transposed into [s][c]
    const float4* v4p = (const float4*)(g_v + (size_t)((b << 10) + c0)*32);
    #pragma unroll
    for (int u = 0; u < 4; u++) {
        int i = t + u*256;
        int row = i >> 3, q = i & 7;
        float4 a4 = v4p[row*8 + q];
        int s = q*4;
        if (s   < 25) v_ts[(s  )*132 + row] = a4.x;
        if (s+1 < 25) v_ts[(s+1)*132 + row] = a4.y;
        if (s+2 < 25) v_ts[(s+2)*132 + row] = a4.z;
        if (s+3 < 25) v_ts[(s+3)*132 + row] = a4.w;
    }
    __syncthreads();

    int w = t >> 5, lane = t & 31;      // warp: 14 n; lane: 4 c
    unsigned long long acc2[4][7] = {};
    #pragma unroll 5
    for (int s = 0; s < 25; s++) {
        float4 v4 = *(const float4*)&v_ts[s*132 + lane*4];
        unsigned long long pv[4] = {pack2(v4.x,v4.x), pack2(v4.y,v4.y),
                                    pack2(v4.z,v4.z), pack2(v4.w,v4.w)};
        const unsigned long long* ap =
            (const unsigned long long*)&attn_ts[s*112 + w*14];
        #pragma unroll
        for (int j = 0; j < 7; j++) {
            unsigned long long a = ap[j];
            fma2(acc2[0][j], pv[0], a);
            fma2(acc2[1][j], pv[1], a);
            fma2(acc2[2][j], pv[2], a);
            fma2(acc2[3][j], pv[3], a);
        }
    }
    float gamma = gamma_p[0];
    #pragma unroll
    for (int ci = 0; ci < 4; ci++) {
        int c = c0 + lane*4 + ci;
        size_t off = (size_t)((b << 10) + c)*784 + n0 + w*14;
        const float2* xr = (const float2*)(x + off);
        float2* orow = (float2*)(out + off);
        #pragma unroll
        for (int j = 0; j < 7; j++) {
            float2 xv = xr[j];
            float2 a = unpack2(acc2[ci][j]);
            orow[j] = make_float2(fmaf(gamma, a.x, xv.x),
                                  fmaf(gamma, a.y, xv.y));
        }
    }
}

// ---------------------------------------------------------------------------
extern "C" void kernel_launch(void* const* d_in, const int* in_sizes, int n_in,
                              void* d_out, int out_size) {
    const float* x_rgb  = (const float*)d_in[0];
    const float* x_skel = (const float*)d_in[1];
    const float* Wq     = (const float*)d_in[2];
    const float* bq     = (const float*)d_in[3];
    const float* Wk     = (const float*)d_in[4];
    const float* bk     = (const float*)d_in[5];
    const float* Wv     = (const float*)d_in[6];
    const float* bv     = (const float*)d_in[7];
    const float* gamma  = (const float*)d_in[8];
    float* out = (float*)d_out;

    k_prep   <<<1739, 128>>>(Wq, bq, Wk, bk, x_skel);
    k_gemm1  <<<dim3(17, 16), 128>>>(Wv, bv);
    k_energy <<<dim3(7, 16, 4), 224>>>(x_rgb);
    k_softmax<<<196, 256>>>();
    k_out    <<<dim3(7, 8, 16), 256>>>(x_rgb, gamma, out);
}

// round 7
// speedup vs baseline: 1.2465x; 1.2465x over previous
#include <cuda_runtime.h>

// ---------------- scratch (device globals; zero-initialized) ---------------
__device__ float g_pooledp[16*256*32];     // [b][cs][32] padded, pads stay 0
__device__ float g_dots[1281];             // Wq^T bk | Wk^T bq | bq.bk
__device__ float g_wqk[1024*256];          // Wq^T Wk  [cr][cs]
__device__ float g_kq[16*1024*32];         // [b][cr][32]
__device__ float g_v[16*1024*32];          // [b][cr][32]
__device__ float g_bqk[16*32];             // [b][32]
__device__ float g_epart[4*16*784*32];     // [z][b][n][32]
__device__ float g_attn_t[16*25*784];      // [b][s][n]  TRANSPOSED attention

// ---------------- packed f32x2 helpers -------------------------------------
__device__ __forceinline__ unsigned long long pack2(float lo, float hi) {
    unsigned long long r;
    asm("mov.b64 %0, {%1,%2};" : "=l"(r) : "f"(lo), "f"(hi));
    return r;
}
__device__ __forceinline__ float2 unpack2(unsigned long long v) {
    float2 r;
    asm("mov.b64 {%0,%1}, %2;" : "=f"(r.x), "=f"(r.y) : "l"(v));
    return r;
}
__device__ __forceinline__ void fma2(unsigned long long& d,
                                     unsigned long long a,
                                     unsigned long long b) {
    asm("fma.rn.f32x2 %0, %1, %2, %0;" : "+l"(d) : "l"(a), "l"(b));
}

// ---------------------------------------------------------------------------
// k_prep: gemm0 (blocks 0..127) | dots (128..138) | pool (139..1738)
// ---------------------------------------------------------------------------
__global__ __launch_bounds__(128) void k_prep(const float* __restrict__ Wq,
                                              const float* __restrict__ bq,
                                              const float* __restrict__ Wk,
                                              const float* __restrict__ bk,
                                              const float* __restrict__ xs_in) {
    __shared__ float sm[1664];
    int bid = blockIdx.x;
    int t = threadIdx.x;

    if (bid < 128) {
        float* As = sm;          // [16][64]
        float* Bs = sm + 1024;   // [16][32]
        int m0 = (bid >> 3) * 64, n0 = (bid & 7) * 32;
        int tx = t & 7, ty = t >> 3;
        unsigned long long acc2[4][2] = {};
        for (int k0 = 0; k0 < 512; k0 += 16) {
            #pragma unroll
            for (int u = 0; u < 8; u++) {
                int idx = t + u * 128;
                int kk = idx >> 6, mm = idx & 63;
                As[kk*64 + mm] = Wq[(k0+kk)*1024 + m0 + mm];
            }
            #pragma unroll
            for (int u = 0; u < 4; u++) {
                int idx = t + u * 128;
                int kk = idx >> 5, nn = idx & 31;
                Bs[kk*32 + nn] = Wk[(k0+kk)*256 + n0 + nn];
            }
            __syncthreads();
            #pragma unroll
            for (int kk = 0; kk < 16; kk++) {
                float4 a4 = *(const float4*)&As[kk*64 + ty*4];
                ulonglong2 b2 = *(const ulonglong2*)&Bs[kk*32 + tx*4];
                unsigned long long pa[4] = {pack2(a4.x,a4.x), pack2(a4.y,a4.y),
                                            pack2(a4.z,a4.z), pack2(a4.w,a4.w)};
                #pragma unroll
                for (int i = 0; i < 4; i++) {
                    fma2(acc2[i][0], pa[i], b2.x);
                    fma2(acc2[i][1], pa[i], b2.y);
                }
            }
            __syncthreads();
        }
        #pragma unroll
        for (int i = 0; i < 4; i++) {
            float2 p0 = unpack2(acc2[i][0]), p1 = unpack2(acc2[i][1]);
            *(float4*)&g_wqk[(m0 + ty*4 + i)*256 + n0 + tx*4] =
                make_float4(p0.x, p0.y, p1.x, p1.y);
        }
    } else if (bid < 136) {
        int c = (bid - 128) * 128 + t;
        float acc = 0.f;
        for (int i = 0; i < 512; i++) acc += Wq[i*1024 + c] * bk[i];
        g_dots[c] = acc;
    } else if (bid < 138) {
        int c = (bid - 136) * 128 + t;
        float acc = 0.f;
        for (int i = 0; i < 512; i++) acc += Wk[i*256 + c] * bq[i];
        g_dots[1024 + c] = acc;
    } else if (bid == 138) {
        float acc = 0.f;
        for (int i = t; i < 512; i += 128) acc += bq[i] * bk[i];
        sm[t] = acc; __syncthreads();
        for (int st = 64; st > 0; st >>= 1) {
            if (t < st) sm[t] += sm[t + st];
            __syncthreads();
        }
        if (t == 0) g_dots[1280] = sm[0];
    } else {
        int r0 = (bid - 139) * 64;
        const float* src = xs_in + (size_t)r0 * 25;
        for (int i = t; i < 1600; i += 128) sm[i] = src[i];
        __syncthreads();
        if (t < 64) {
            float s = 0.f;
            #pragma unroll
            for (int w = 0; w < 25; w++) s += sm[t*25 + w];
            int o = r0 + t;
            int bc = o / 25, s_idx = o - bc * 25;
            g_pooledp[bc*32 + s_idx] = s * (1.0f / 25.0f);
        }
    }
}

// ---------------------------------------------------------------------------
// k_gemm1: [kq; v; bqk](b) = [Wqk; Wv; wkbq] @ pooledp_b + bias
// grid(17, 16), 128 thr. BM=128, S=32, BK=32. thread 8m x 4s.
// ---------------------------------------------------------------------------
__global__ __launch_bounds__(128) void k_gemm1(const float* __restrict__ Wv,
                                               const float* __restrict__ bv) {
    __shared__ float As[32*132];
    __shared__ float Bs[32*32];
    int bx = blockIdx.x;
    int b  = blockIdx.y;
    int m0 = bx * 128;
    int t = threadIdx.x;
    int tx = t & 7, ty = t >> 3;
    unsigned long long acc2[8][2] = {};

    const float* arow;
    if (bx < 8)       arow = g_wqk + (size_t)(m0 + t) * 256;
    else if (bx < 16) arow = Wv + (size_t)(m0 - 1024 + t) * 256;
    else              arow = g_dots + 1024;

    for (int k0 = 0; k0 < 256; k0 += 32) {
        if (bx < 16 || t == 0) {
            #pragma unroll
            for (int u = 0; u < 8; u++) {
                float4 a4 = *(const float4*)&arow[k0 + u*4];
                As[(u*4+0)*132 + t] = a4.x;
                As[(u*4+1)*132 + t] = a4.y;
                As[(u*4+2)*132 + t] = a4.z;
                As[(u*4+3)*132 + t] = a4.w;
            }
        } else {
            #pragma unroll
            for (int u = 0; u < 32; u++) As[u*132 + t] = 0.f;
        }
        const float4* bsrc = (const float4*)(g_pooledp + ((b << 8) + k0) * 32);
        float4* bs4 = (float4*)Bs;
        bs4[t] = bsrc[t];
        bs4[t + 128] = bsrc[t + 128];
        __syncthreads();
        #pragma unroll 8
        for (int kk = 0; kk < 32; kk++) {
            float4 alo = *(const float4*)&As[kk*132 + ty*8];
            float4 ahi = *(const float4*)&As[kk*132 + ty*8 + 4];
            ulonglong2 b2 = *(const ulonglong2*)&Bs[kk*32 + tx*4];
            unsigned long long pa[8] = {
                pack2(alo.x,alo.x), pack2(alo.y,alo.y),
                pack2(alo.z,alo.z), pack2(alo.w,alo.w),
                pack2(ahi.x,ahi.x), pack2(ahi.y,ahi.y),
                pack2(ahi.z,ahi.z), pack2(ahi.w,ahi.w)};
            #pragma unroll
            for (int i = 0; i < 8; i++) {
                fma2(acc2[i][0], pa[i], b2.x);
                fma2(acc2[i][1], pa[i], b2.y);
            }
        }
        __syncthreads();
    }
    int s0 = tx * 4;
    #pragma unroll
    for (int i = 0; i < 8; i++) {
        int m = m0 + ty*8 + i;
        float2 p0 = unpack2(acc2[i][0]), p1 = unpack2(acc2[i][1]);
        if (bx < 8) {
            float d = g_dots[m];
            *(float4*)&g_kq[((b << 10) + m)*32 + s0] =
                make_float4(p0.x+d, p0.y+d, p1.x+d, p1.y+d);
        } else if (bx < 16) {
            float d = bv[m - 1024];
            *(float4*)&g_v[((b << 10) + (m - 1024))*32 + s0] =
                make_float4(p0.x+d, p0.y+d, p1.x+d, p1.y+d);
        } else if (m == 2048) {
            float d = g_dots[1280];
            *(float4*)&g_bqk[b*32 + s0] =
                make_float4(p0.x+d, p0.y+d, p1.x+d, p1.y+d);
        }
    }
}

// ---------------------------------------------------------------------------
// k_energy: epart[z,b,n,s] = sum_{c in z-chunk} x[c,n]*kq[c,s]
// grid(7 n-tiles of 112, 16 b, 4 z), 224 thr. thread 4n x 4s.
// ---------------------------------------------------------------------------
__global__ __launch_bounds__(224) void k_energy(const float* __restrict__ x) {
    __shared__ float xs[64*112];
    __shared__ float kqs[64*32];
    int n0 = blockIdx.x * 112;
    int b  = blockIdx.y;
    int z  = blockIdx.z;
    int t = threadIdx.x;
    int nq = t % 28, sg = t / 28;
    unsigned long long acc2[4][2] = {};

    for (int cz = 0; cz < 4; cz++) {
        int cbase = z * 256 + cz * 64;
        const float4* xsrc = (const float4*)x
            + (size_t)((b << 10) + cbase) * 196 + (n0 >> 2);
        #pragma unroll
        for (int u = 0; u < 8; u++) {
            int cc = sg + u * 8;
            *(float4*)&xs[cc*112 + nq*4] = xsrc[(size_t)cc*196 + nq];
        }
        const float4* kq4 = (const float4*)(g_kq + (size_t)((b << 10) + cbase)*32);
        float4* kqs4 = (float4*)kqs;
        kqs4[t] = kq4[t];
        if (t + 224 < 512) kqs4[t + 224] = kq4[t + 224];
        if (t < 512 - 448) kqs4[t + 448] = kq4[t + 448];
        __syncthreads();
        #pragma unroll 8
        for (int cc = 0; cc < 64; cc++) {
            float4 x4 = *(const float4*)&xs[cc*112 + nq*4];
            ulonglong2 k2 = *(const ulonglong2*)&kqs[cc*32 + sg*4];
            unsigned long long px[4] = {pack2(x4.x,x4.x), pack2(x4.y,x4.y),
                                        pack2(x4.z,x4.z), pack2(x4.w,x4.w)};
            #pragma unroll
            for (int i = 0; i < 4; i++) {
                fma2(acc2[i][0], px[i], k2.x);
                fma2(acc2[i][1], px[i], k2.y);
            }
        }
        __syncthreads();
    }
    float* ep = g_epart + (size_t)(z*16 + b)*784*32;
    #pragma unroll
    for (int i = 0; i < 4; i++) {
        int n = n0 + nq*4 + i;
        float2 p0 = unpack2(acc2[i][0]), p1 = unpack2(acc2[i][1]);
        *(float4*)&ep[(size_t)n*32 + sg*4] = make_float4(p0.x, p0.y, p1.x, p1.y);
    }
}

// ---------------------------------------------------------------------------
// k_softmax: 4 threads/pixel, split over s, quad shfl reduce.
// Writes TRANSPOSED attn [b][s][n]. grid(196), 256 thr.
// ---------------------------------------------------------------------------
__global__ __launch_bounds__(256) void k_softmax() {
    int t = threadIdx.x;
    int gp = blockIdx.x * 64 + (t >> 2);
    int q = t & 3;
    int b = gp / 784, n = gp - b * 784;

    const size_t part = (size_t)16*784*32;
    const float* base = g_epart + ((size_t)b*784 + n)*32 + q*8;
    float4 lo = *(const float4*)base;
    float4 hi = *(const float4*)(base + 4);
    #pragma unroll
    for (int z = 1; z < 4; z++) {
        float4 l2 = *(const float4*)(base + z*part);
        float4 h2 = *(const float4*)(base + z*part + 4);
        lo.x += l2.x; lo.y += l2.y; lo.z += l2.z; lo.w += l2.w;
        hi.x += h2.x; hi.y += h2.y; hi.z += h2.z; hi.w += h2.w;
    }
    float e[8] = {lo.x, lo.y, lo.z, lo.w, hi.x, hi.y, hi.z, hi.w};
    #pragma unroll
    for (int i = 0; i < 8; i++) {
        int s = q*8 + i;
        e[i] = (s < 25) ? e[i] + g_bqk[b*32 + s] : -1e30f;
    }
    float mx = e[0];
    #pragma unroll
    for (int i = 1; i < 8; i++) mx = fmaxf(mx, e[i]);
    mx = fmaxf(mx, __shfl_xor_sync(0xffffffffu, mx, 1));
    mx = fmaxf(mx, __shfl_xor_sync(0xffffffffu, mx, 2));
    float sum = 0.f;
    #pragma unroll
    for (int i = 0; i < 8; i++) { e[i] = __expf(e[i] - mx); sum += e[i]; }
    sum += __shfl_xor_sync(0xffffffffu, sum, 1);
    sum += __shfl_xor_sync(0xffffffffu, sum, 2);
    float inv = 1.f / sum;
    float* at = g_attn_t + (size_t)b*25*784 + n;
    #pragma unroll
    for (int i = 0; i < 8; i++) {
        int s = q*8 + i;
        if (s < 25) at[(size_t)s*784] = e[i] * inv;
    }
}

// ---------------------------------------------------------------------------
// k_out: out[c,n] = x[c,n] + gamma * sum_s v[c,s]*attn_t[s,n]
// grid(7 n-tiles of 112, 16 c-tiles of 64, 16 b), 224 thr. thread 4c x 8n.
// Lanes along n: coalesced global x/out; attn loaded straight from attn_t.
// ---------------------------------------------------------------------------
__global__ __launch_bounds__(224) void k_out(const float* __restrict__ x,
                                             const float* __restrict__ gamma_p,
                                             float* __restrict__ out) {
    __shared__ float attn_ts[25*116];   // [s][n], row pad 116 (29 float4)
    __shared__ float v_ts[25*68];       // [s][c] transpose load
    int n0 = blockIdx.x * 112;
    int c0 = blockIdx.y * 64;
    int b  = blockIdx.z;
    int t = threadIdx.x;

    // attn: straight coalesced copy, 25 rows x 28 float4
    const float4* at4 = (const float4*)(g_attn_t + (size_t)b*25*784 + n0);
    #pragma unroll
    for (int u = 0; u < 4; u++) {
        int i = t + u*224;
        if (i < 700) {
            int s = i / 28, q = i - s*28;
            ((float4*)attn_ts)[s*29 + q] = at4[(size_t)s*196 + q];
        }
    }
    // v: 64 rows x 8 quads, transposed into [s][c]
    const float4* v4p = (const float4*)(g_v + (size_t)((b << 10) + c0)*32);
    #pragma unroll
    for (int u = 0; u < 3; u++) {
        int i = t + u*224;
        if (i < 512) {
            int row = i >> 3, q = i & 7;
            float4 a4 = v4p[row*8 + q];
            int s = q*4;
            if (s   < 25) v_ts[(s  )*68 + row] = a4.x;
            if (s+1 < 25) v_ts[(s+1)*68 + row] = a4.y;
            if (s+2 < 25) v_ts[(s+2)*68 + row] = a4.z;
            if (s+3 < 25) v_ts[(s+3)*68 + row] = a4.w;
        }
    }
    __syncthreads();

    int ng = t % 14, cq = t / 14;      // 14 n-octets x 16 c-quads
    unsigned long long acc2[4][4] = {};
    #pragma unroll
    for (int s = 0; s < 25; s++) {
        float4 v4 = *(const float4*)&v_ts[s*68 + cq*4];
        const ulonglong2* ap = (const ulonglong2*)&attn_ts[s*116 + ng*8];
        ulonglong2 A0 = ap[0], A1 = ap[1];
        unsigned long long pv[4] = {pack2(v4.x,v4.x), pack2(v4.y,v4.y),
                                    pack2(v4.z,v4.z), pack2(v4.w,v4.w)};
        #pragma unroll
        for (int i = 0; i < 4; i++) {
            fma2(acc2[i][0], pv[i], A0.x);
            fma2(acc2[i][1], pv[i], A0.y);
            fma2(acc2[i][2], pv[i], A1.x);
            fma2(acc2[i][3], pv[i], A1.y);
        }
    }
    float gamma = gamma_p[0];
    #pragma unroll
    for (int i = 0; i < 4; i++) {
        int c = c0 + cq*4 + i;
        size_t off = (size_t)((b << 10) + c)*784 + n0 + ng*8;
        const float* xr = x + off;
        float* orow = out + off;
        float2 q0 = unpack2(acc2[i][0]), q1 = unpack2(acc2[i][1]);
        float2 q2 = unpack2(acc2[i][2]), q3 = unpack2(acc2[i][3]);
        float4 xa = *(const float4*)xr;
        float4 xc = *(const float4*)(xr + 4);
        *(float4*)orow = make_float4(fmaf(gamma,q0.x,xa.x), fmaf(gamma,q0.y,xa.y),
                                     fmaf(gamma,q1.x,xa.z), fmaf(gamma,q1.y,xa.w));
        *(float4*)(orow+4) = make_float4(fmaf(gamma,q2.x,xc.x), fmaf(gamma,q2.y,xc.y),
                                         fmaf(gamma,q3.x,xc.z), fmaf(gamma,q3.y,xc.w));
    }
}

// ---------------------------------------------------------------------------
extern "C" void kernel_launch(void* const* d_in, const int* in_sizes, int n_in,
                              void* d_out, int out_size) {
    const float* x_rgb  = (const float*)d_in[0];
    const float* x_skel = (const float*)d_in[1];
    const float* Wq     = (const float*)d_in[2];
    const float* bq     = (const float*)d_in[3];
    const float* Wk     = (const float*)d_in[4];
    const float* bk     = (const float*)d_in[5];
    const float* Wv     = (const float*)d_in[6];
    const float* bv     = (const float*)d_in[7];
    const float* gamma  = (const float*)d_in[8];
    float* out = (float*)d_out;

    k_prep   <<<1739, 128>>>(Wq, bq, Wk, bk, x_skel);
    k_gemm1  <<<dim3(17, 16), 128>>>(Wv, bv);
    k_energy <<<dim3(7, 16, 4), 224>>>(x_rgb);
    k_softmax<<<196, 256>>>();
    k_out    <<<dim3(7, 16, 16), 224>>>(x_rgb, gamma, out);
}

// round 8
// speedup vs baseline: 1.2620x; 1.0124x over previous
#include <cuda_runtime.h>

// ---------------- scratch (device globals; zero-initialized) ---------------
__device__ float g_pooledp[16*256*32];     // [b][cs][32] padded, pads stay 0
__device__ float g_dots[1281];             // Wq^T bk | Wk^T bq | bq.bk
__device__ float g_wqk[1024*256];          // Wq^T Wk  [cr][cs]
__device__ float g_kq[16*1024*32];         // [b][cr][32]
__device__ float g_v[16*1024*32];          // [b][cr][32]
__device__ float g_bqk[16*32];             // [b][32]
__device__ float g_epart[4*16*784*32];     // [z][b][n][32]
__device__ float g_attn_t[16*25*784];      // [b][s][n]  TRANSPOSED attention

// ---------------- packed f32x2 helpers -------------------------------------
__device__ __forceinline__ unsigned long long pack2(float lo, float hi) {
    unsigned long long r;
    asm("mov.b64 %0, {%1,%2};" : "=l"(r) : "f"(lo), "f"(hi));
    return r;
}
__device__ __forceinline__ float2 unpack2(unsigned long long v) {
    float2 r;
    asm("mov.b64 {%0,%1}, %2;" : "=f"(r.x), "=f"(r.y) : "l"(v));
    return r;
}
__device__ __forceinline__ void fma2(unsigned long long& d,
                                     unsigned long long a,
                                     unsigned long long b) {
    asm("fma.rn.f32x2 %0, %1, %2, %0;" : "+l"(d) : "l"(a), "l"(b));
}

// ---------------------------------------------------------------------------
// k_prep: gemm0 (blocks 0..255) | dots (256..266) | pool (267..1866)
// gemm0: BM=32, BN=32, BK=16 -> 256 blocks, thread tile 2m x 4s.
// ---------------------------------------------------------------------------
__global__ __launch_bounds__(128) void k_prep(const float* __restrict__ Wq,
                                              const float* __restrict__ bq,
                                              const float* __restrict__ Wk,
                                              const float* __restrict__ bk,
                                              const float* __restrict__ xs_in) {
    __shared__ float sm[1664];
    int bid = blockIdx.x;
    int t = threadIdx.x;

    if (bid < 256) {
        float* As = sm;          // [16][32]
        float* Bs = sm + 512;    // [16][32]
        int m0 = (bid >> 3) * 32, n0 = (bid & 7) * 32;
        int tx = t & 7, ty = t >> 3;       // 8 s-quads x 16 m-pairs
        unsigned long long acc2[2][2] = {};
        for (int k0 = 0; k0 < 512; k0 += 16) {
            #pragma unroll
            for (int u = 0; u < 4; u++) {
                int idx = t + u * 128;
                int kk = idx >> 5, mm = idx & 31;
                As[idx] = Wq[(k0+kk)*1024 + m0 + mm];
                Bs[idx] = Wk[(k0+kk)*256 + n0 + mm];
            }
            __syncthreads();
            #pragma unroll
            for (int kk = 0; kk < 16; kk++) {
                float2 a2 = *(const float2*)&As[kk*32 + ty*2];
                ulonglong2 b2 = *(const ulonglong2*)&Bs[kk*32 + tx*4];
                unsigned long long pa0 = pack2(a2.x, a2.x);
                unsigned long long pa1 = pack2(a2.y, a2.y);
                fma2(acc2[0][0], pa0, b2.x);
                fma2(acc2[0][1], pa0, b2.y);
                fma2(acc2[1][0], pa1, b2.x);
                fma2(acc2[1][1], pa1, b2.y);
            }
            __syncthreads();
        }
        #pragma unroll
        for (int i = 0; i < 2; i++) {
            float2 p0 = unpack2(acc2[i][0]), p1 = unpack2(acc2[i][1]);
            *(float4*)&g_wqk[(m0 + ty*2 + i)*256 + n0 + tx*4] =
                make_float4(p0.x, p0.y, p1.x, p1.y);
        }
    } else if (bid < 264) {
        int c = (bid - 256) * 128 + t;
        float acc = 0.f;
        for (int i = 0; i < 512; i++) acc += Wq[i*1024 + c] * bk[i];
        g_dots[c] = acc;
    } else if (bid < 266) {
        int c = (bid - 264) * 128 + t;
        float acc = 0.f;
        for (int i = 0; i < 512; i++) acc += Wk[i*256 + c] * bq[i];
        g_dots[1024 + c] = acc;
    } else if (bid == 266) {
        float acc = 0.f;
        for (int i = t; i < 512; i += 128) acc += bq[i] * bk[i];
        sm[t] = acc; __syncthreads();
        for (int st = 64; st > 0; st >>= 1) {
            if (t < st) sm[t] += sm[t + st];
            __syncthreads();
        }
        if (t == 0) g_dots[1280] = sm[0];
    } else {
        int r0 = (bid - 267) * 64;
        const float* src = xs_in + (size_t)r0 * 25;
        for (int i = t; i < 1600; i += 128) sm[i] = src[i];
        __syncthreads();
        if (t < 64) {
            float s = 0.f;
            #pragma unroll
            for (int w = 0; w < 25; w++) s += sm[t*25 + w];
            int o = r0 + t;
            int bc = o / 25, s_idx = o - bc * 25;
            g_pooledp[bc*32 + s_idx] = s * (1.0f / 25.0f);
        }
    }
}

// ---------------------------------------------------------------------------
// k_gemm1: [kq; v; bqk](b) = [Wqk; Wv; wkbq] @ pooledp_b + bias
// grid(17, 16), 256 thr (8 warps). BM=128, S=32, BK=32. thread 4m x 4s.
// ---------------------------------------------------------------------------
__global__ __launch_bounds__(256) void k_gemm1(const float* __restrict__ Wv,
                                               const float* __restrict__ bv) {
    __shared__ float As[32*132];
    __shared__ float Bs[32*32];
    int bx = blockIdx.x;
    int b  = blockIdx.y;
    int m0 = bx * 128;
    int t = threadIdx.x;
    int row = t >> 1, half = t & 1;     // A-load: 2 threads per m-row
    int tx = t & 7, ty = t >> 3;        // compute: 8 s-quads x 32 m-quads
    unsigned long long acc2[4][2] = {};

    const float* arow;
    bool arow_valid;
    if (bx < 8)       { arow = g_wqk + (size_t)(m0 + row) * 256; arow_valid = true; }
    else if (bx < 16) { arow = Wv + (size_t)(m0 - 1024 + row) * 256; arow_valid = true; }
    else              { arow = g_dots + 1024; arow_valid = (row == 0); }

    for (int k0 = 0; k0 < 256; k0 += 32) {
        if (arow_valid) {
            #pragma unroll
            for (int u = 0; u < 4; u++) {
                int koff = half*16 + u*4;
                float4 a4 = *(const float4*)&arow[k0 + koff];
                As[(koff+0)*132 + row] = a4.x;
                As[(koff+1)*132 + row] = a4.y;
                As[(koff+2)*132 + row] = a4.z;
                As[(koff+3)*132 + row] = a4.w;
            }
        } else {
            #pragma unroll
            for (int u = 0; u < 4; u++) {
                int koff = half*16 + u*4;
                As[(koff+0)*132 + row] = 0.f;
                As[(koff+1)*132 + row] = 0.f;
                As[(koff+2)*132 + row] = 0.f;
                As[(koff+3)*132 + row] = 0.f;
            }
        }
        const float4* bsrc = (const float4*)(g_pooledp + ((b << 8) + k0) * 32);
        ((float4*)Bs)[t] = bsrc[t];
        __syncthreads();
        #pragma unroll 8
        for (int kk = 0; kk < 32; kk++) {
            float4 a4 = *(const float4*)&As[kk*132 + ty*4];
            ulonglong2 b2 = *(const ulonglong2*)&Bs[kk*32 + tx*4];
            unsigned long long pa[4] = {pack2(a4.x,a4.x), pack2(a4.y,a4.y),
                                        pack2(a4.z,a4.z), pack2(a4.w,a4.w)};
            #pragma unroll
            for (int i = 0; i < 4; i++) {
                fma2(acc2[i][0], pa[i], b2.x);
                fma2(acc2[i][1], pa[i], b2.y);
            }
        }
        __syncthreads();
    }
    int s0 = tx * 4;
    #pragma unroll
    for (int i = 0; i < 4; i++) {
        int m = m0 + ty*4 + i;
        float2 p0 = unpack2(acc2[i][0]), p1 = unpack2(acc2[i][1]);
        if (bx < 8) {
            float d = g_dots[m];
            *(float4*)&g_kq[((b << 10) + m)*32 + s0] =
                make_float4(p0.x+d, p0.y+d, p1.x+d, p1.y+d);
        } else if (bx < 16) {
            float d = bv[m - 1024];
            *(float4*)&g_v[((b << 10) + (m - 1024))*32 + s0] =
                make_float4(p0.x+d, p0.y+d, p1.x+d, p1.y+d);
        } else if (m == 2048) {
            float d = g_dots[1280];
            *(float4*)&g_bqk[b*32 + s0] =
                make_float4(p0.x+d, p0.y+d, p1.x+d, p1.y+d);
        }
    }
}

// ---------------------------------------------------------------------------
// k_energy: epart[z,b,n,s] = sum_{c in z-chunk} x[c,n]*kq[c,s]
// grid(7 n-tiles of 112, 16 b, 4 z), 224 thr. thread 4n x 4s.
// ---------------------------------------------------------------------------
__global__ __launch_bounds__(224) void k_energy(const float* __restrict__ x) {
    __shared__ float xs[64*112];
    __shared__ float kqs[64*32];
    int n0 = blockIdx.x * 112;
    int b  = blockIdx.y;
    int z  = blockIdx.z;
    int t = threadIdx.x;
    int nq = t % 28, sg = t / 28;
    unsigned long long acc2[4][2] = {};

    for (int cz = 0; cz < 4; cz++) {
        int cbase = z * 256 + cz * 64;
        const float4* xsrc = (const float4*)x
            + (size_t)((b << 10) + cbase) * 196 + (n0 >> 2);
        #pragma unroll
        for (int u = 0; u < 8; u++) {
            int cc = sg + u * 8;
            *(float4*)&xs[cc*112 + nq*4] = xsrc[(size_t)cc*196 + nq];
        }
        const float4* kq4 = (const float4*)(g_kq + (size_t)((b << 10) + cbase)*32);
        float4* kqs4 = (float4*)kqs;
        kqs4[t] = kq4[t];
        if (t + 224 < 512) kqs4[t + 224] = kq4[t + 224];
        if (t < 512 - 448) kqs4[t + 448] = kq4[t + 448];
        __syncthreads();
        #pragma unroll 8
        for (int cc = 0; cc < 64; cc++) {
            float4 x4 = *(const float4*)&xs[cc*112 + nq*4];
            ulonglong2 k2 = *(const ulonglong2*)&kqs[cc*32 + sg*4];
            unsigned long long px[4] = {pack2(x4.x,x4.x), pack2(x4.y,x4.y),
                                        pack2(x4.z,x4.z), pack2(x4.w,x4.w)};
            #pragma unroll
            for (int i = 0; i < 4; i++) {
                fma2(acc2[i][0], px[i], k2.x);
                fma2(acc2[i][1], px[i], k2.y);
            }
        }
        __syncthreads();
    }
    float* ep = g_epart + (size_t)(z*16 + b)*784*32;
    #pragma unroll
    for (int i = 0; i < 4; i++) {
        int n = n0 + nq*4 + i;
        float2 p0 = unpack2(acc2[i][0]), p1 = unpack2(acc2[i][1]);
        *(float4*)&ep[(size_t)n*32 + sg*4] = make_float4(p0.x, p0.y, p1.x, p1.y);
    }
}

// ---------------------------------------------------------------------------
// k_softmax: 4 threads/pixel, split over s, quad shfl reduce.
// Writes TRANSPOSED attn [b][s][n]. grid(392), 128 thr.
// ---------------------------------------------------------------------------
__global__ __launch_bounds__(128) void k_softmax() {
    int t = threadIdx.x;
    int gp = blockIdx.x * 32 + (t >> 2);
    int q = t & 3;
    int b = gp / 784, n = gp - b * 784;

    const size_t part = (size_t)16*784*32;
    const float* base = g_epart + ((size_t)b*784 + n)*32 + q*8;
    float4 lo = *(const float4*)base;
    float4 hi = *(const float4*)(base + 4);
    #pragma unroll
    for (int z = 1; z < 4; z++) {
        float4 l2 = *(const float4*)(base + z*part);
        float4 h2 = *(const float4*)(base + z*part + 4);
        lo.x += l2.x; lo.y += l2.y; lo.z += l2.z; lo.w += l2.w;
        hi.x += h2.x; hi.y += h2.y; hi.z += h2.z; hi.w += h2.w;
    }
    float e[8] = {lo.x, lo.y, lo.z, lo.w, hi.x, hi.y, hi.z, hi.w};
    #pragma unroll
    for (int i = 0; i < 8; i++) {
        int s = q*8 + i;
        e[i] = (s < 25) ? e[i] + g_bqk[b*32 + s] : -1e30f;
    }
    float mx = e[0];
    #pragma unroll
    for (int i = 1; i < 8; i++) mx = fmaxf(mx, e[i]);
    mx = fmaxf(mx, __shfl_xor_sync(0xffffffffu, mx, 1));
    mx = fmaxf(mx, __shfl_xor_sync(0xffffffffu, mx, 2));
    float sum = 0.f;
    #pragma unroll
    for (int i = 0; i < 8; i++) { e[i] = __expf(e[i] - mx); sum += e[i]; }
    sum += __shfl_xor_sync(0xffffffffu, sum, 1);
    sum += __shfl_xor_sync(0xffffffffu, sum, 2);
    float inv = 1.f / sum;
    float* at = g_attn_t + (size_t)b*25*784 + n;
    #pragma unroll
    for (int i = 0; i < 8; i++) {
        int s = q*8 + i;
        if (s < 25) at[(size_t)s*784] = e[i] * inv;
    }
}

// ---------------------------------------------------------------------------
// k_out: out[c,n] = x[c,n] + gamma * sum_s v[c,s]*attn_t[s,n]
// grid(7 n-tiles of 112, 16 c-tiles of 64, 16 b), 224 thr. thread 4c x 8n.
// ---------------------------------------------------------------------------
__global__ __launch_bounds__(224) void k_out(const float* __restrict__ x,
                                             const float* __restrict__ gamma_p,
                                             float* __restrict__ out) {
    __shared__ float attn_ts[25*116];   // [s][n], row pad 116 (29 float4)
    __shared__ float v_ts[25*68];       // [s][c] transpose load
    int n0 = blockIdx.x * 112;
    int c0 = blockIdx.y * 64;
    int b  = blockIdx.z;
    int t = threadIdx.x;

    const float4* at4 = (const float4*)(g_attn_t + (size_t)b*25*784 + n0);
    #pragma unroll
    for (int u = 0; u < 4; u++) {
        int i = t + u*224;
        if (i < 700) {
            int s = i / 28, q = i - s*28;
            ((float4*)attn_ts)[s*29 + q] = at4[(size_t)s*196 + q];
        }
    }
    const float4* v4p = (const float4*)(g_v + (size_t)((b << 10) + c0)*32);
    #pragma unroll
    for (int u = 0; u < 3; u++) {
        int i = t + u*224;
        if (i < 512) {
            int row = i >> 3, q = i & 7;
            float4 a4 = v4p[row*8 + q];
            int s = q*4;
            if (s   < 25) v_ts[(s  )*68 + row] = a4.x;
            if (s+1 < 25) v_ts[(s+1)*68 + row] = a4.y;
            if (s+2 < 25) v_ts[(s+2)*68 + row] = a4.z;
            if (s+3 < 25) v_ts[(s+3)*68 + row] = a4.w;
        }
    }
    __syncthreads();

    int ng = t % 14, cq = t / 14;
    unsigned long long acc2[4][4] = {};
    #pragma unroll
    for (int s = 0; s < 25; s++) {
        float4 v4 = *(const float4*)&v_ts[s*68 + cq*4];
        const ulonglong2* ap = (const ulonglong2*)&attn_ts[s*116 + ng*8];
        ulonglong2 A0 = ap[0], A1 = ap[1];
        unsigned long long pv[4] = {pack2(v4.x,v4.x), pack2(v4.y,v4.y),
                                    pack2(v4.z,v4.z), pack2(v4.w,v4.w)};
        #pragma unroll
        for (int i = 0; i < 4; i++) {
            fma2(acc2[i][0], pv[i], A0.x);
            fma2(acc2[i][1], pv[i], A0.y);
            fma2(acc2[i][2], pv[i], A1.x);
            fma2(acc2[i][3], pv[i], A1.y);
        }
    }
    float gamma = gamma_p[0];
    #pragma unroll
    for (int i = 0; i < 4; i++) {
        int c = c0 + cq*4 + i;
        size_t off = (size_t)((b << 10) + c)*784 + n0 + ng*8;
        const float* xr = x + off;
        float* orow = out + off;
        float2 q0 = unpack2(acc2[i][0]), q1 = unpack2(acc2[i][1]);
        float2 q2 = unpack2(acc2[i][2]), q3 = unpack2(acc2[i][3]);
        float4 xa = *(const float4*)xr;
        float4 xc = *(const float4*)(xr + 4);
        *(float4*)orow = make_float4(fmaf(gamma,q0.x,xa.x), fmaf(gamma,q0.y,xa.y),
                                     fmaf(gamma,q1.x,xa.z), fmaf(gamma,q1.y,xa.w));
        *(float4*)(orow+4) = make_float4(fmaf(gamma,q2.x,xc.x), fmaf(gamma,q2.y,xc.y),
                                         fmaf(gamma,q3.x,xc.z), fmaf(gamma,q3.y,xc.w));
    }
}

// ---------------------------------------------------------------------------
extern "C" void kernel_launch(void* const* d_in, const int* in_sizes, int n_in,
                              void* d_out, int out_size) {
    const float* x_rgb  = (const float*)d_in[0];
    const float* x_skel = (const float*)d_in[1];
    const float* Wq     = (const float*)d_in[2];
    const float* bq     = (const float*)d_in[3];
    const float* Wk     = (const float*)d_in[4];
    const float* bk     = (const float*)d_in[5];
    const float* Wv     = (const float*)d_in[6];
    const float* bv     = (const float*)d_in[7];
    const float* gamma  = (const float*)d_in[8];
    float* out = (float*)d_out;

    k_prep   <<<1867, 128>>>(Wq, bq, Wk, bk, x_skel);
    k_gemm1  <<<dim3(17, 16), 256>>>(Wv, bv);
    k_energy <<<dim3(7, 16, 4), 224>>>(x_rgb);
    k_softmax<<<392, 128>>>();
    k_out    <<<dim3(7, 16, 16), 224>>>(x_rgb, gamma, out);
}